// round 15
// baseline (speedup 1.0000x reference)
#include <cuda_runtime.h>
#include <cuda_fp16.h>
#include <cstdint>
#include <cstddef>

#define DI __device__ __forceinline__

// ---------------- constants ----------------
constexpr int BM = 128, BN = 32, BK = 64, THREADS = 256;
constexpr int DIMK = 1024;
constexpr int BATCH = 16384;
constexpr int KTOT = 2048;
constexpr int CHUNKS = 32;                        // 2048 / 64
constexpr size_t PLANE = (size_t)BATCH * DIMK;

// A: sw128-swizzled rows of 128B (64 halves). B: 4 gate tiles, 64k x 32n, stride 80.
constexpr uint32_t A_BYTES  = 128 * 128;          // 16384
constexpr uint32_t BG_STRIDE = 80;                // 64B data + 16B pad
constexpr uint32_t BG_BYTES  = 64 * BG_STRIDE;    // 5120 per gate
constexpr uint32_t B_BYTES   = 4 * BG_BYTES;      // 20480
constexpr uint32_t STG = A_BYTES + B_BYTES;       // 36864
constexpr uint32_t SMEM_TOTAL = 3 * STG;          // 110592 -> 2 CTAs/SM (216KB)

// z-exchange layout in reused smem: [gate][128][36] floats
constexpr uint32_t ZS_G = 128 * 36;

// ---------------- device scratch ----------------
__device__ __half g_XH[(size_t)BATCH * KTOT];     // [m][k]: X | H
__device__ __half g_W[(size_t)4 * KTOT * DIMK];   // [gate][k][n]

// ---------------- PTX helpers ----------------
DI uint32_t smem_u32(const void* p) {
    uint32_t a;
    asm("{ .reg .u64 t; cvta.to.shared.u64 t, %1; cvt.u32.u64 %0, t; }" : "=r"(a) : "l"(p));
    return a;
}
DI uint32_t sw128(uint32_t o) { return o ^ ((o >> 3) & 0x70); }
DI void cpasync16(uint32_t dst, const void* src) {
    asm volatile("cp.async.cg.shared.global [%0], [%1], 16;" :: "r"(dst), "l"(src) : "memory");
}
DI void cpcommit() { asm volatile("cp.async.commit_group;" ::: "memory"); }
template<int N> DI void cpwait() { asm volatile("cp.async.wait_group %0;" :: "n"(N) : "memory"); }
DI void ldsm4(uint32_t* r, uint32_t a) {
    asm volatile("ldmatrix.sync.aligned.m8n8.x4.shared.b16 {%0,%1,%2,%3}, [%4];"
                 : "=r"(r[0]), "=r"(r[1]), "=r"(r[2]), "=r"(r[3]) : "r"(a));
}
DI void ldsm4t(uint32_t* r, uint32_t a) {
    asm volatile("ldmatrix.sync.aligned.m8n8.x4.trans.shared.b16 {%0,%1,%2,%3}, [%4];"
                 : "=r"(r[0]), "=r"(r[1]), "=r"(r[2]), "=r"(r[3]) : "r"(a));
}
DI void mma16(float* d, const uint32_t* a, uint32_t b0, uint32_t b1) {
    asm volatile(
        "mma.sync.aligned.m16n8k16.row.col.f32.f16.f16.f32 "
        "{%0,%1,%2,%3},{%4,%5,%6,%7},{%8,%9},{%0,%1,%2,%3};"
        : "+f"(d[0]), "+f"(d[1]), "+f"(d[2]), "+f"(d[3])
        : "r"(a[0]), "r"(a[1]), "r"(a[2]), "r"(a[3]), "r"(b0), "r"(b1));
}

// ---------------- merged prep: fp16 conversion of X|H and W ----------------
__global__ void __launch_bounds__(256)
convAll(const float* __restrict__ X, const float* __restrict__ H,
        const float* __restrict__ Wfx, const float* __restrict__ Wfh,
        const float* __restrict__ Wix, const float* __restrict__ Wih,
        const float* __restrict__ Wox, const float* __restrict__ Woh,
        const float* __restrict__ Wcx, const float* __restrict__ Wch)
{
    const int t = threadIdx.x;
    if (blockIdx.x < BATCH) {
        const uint32_t m = blockIdx.x;
        const float* src = (t < 128) ? X + ((size_t)m << 10) + 8 * t
                                     : H + ((size_t)m << 10) + 8 * (t - 128);
        const float4 v0 = reinterpret_cast<const float4*>(src)[0];
        const float4 v1 = reinterpret_cast<const float4*>(src)[1];
        __half2 h[4];
        h[0] = __floats2half2_rn(v0.x, v0.y);
        h[1] = __floats2half2_rn(v0.z, v0.w);
        h[2] = __floats2half2_rn(v1.x, v1.y);
        h[3] = __floats2half2_rn(v1.z, v1.w);
        *reinterpret_cast<uint4*>(g_XH + ((uint32_t)m << 11) + 8 * t) = *reinterpret_cast<uint4*>(h);
    } else {
        const uint32_t row = (blockIdx.x - BATCH) * 2 + (t >> 7);   // 2 W-rows per block
        const uint32_t gate = row >> 11;
        const uint32_t k = row & 2047;
        const uint32_t t7 = t & 127;
        const float* Wx = (gate == 0) ? Wfx : (gate == 1) ? Wix : (gate == 2) ? Wox : Wcx;
        const float* Wh = (gate == 0) ? Wfh : (gate == 1) ? Wih : (gate == 2) ? Woh : Wch;
        const float* src = ((k < 1024) ? Wx + ((size_t)k << 10)
                                       : Wh + ((size_t)(k - 1024) << 10)) + 8 * t7;
        const float4 v0 = reinterpret_cast<const float4*>(src)[0];
        const float4 v1 = reinterpret_cast<const float4*>(src)[1];
        __half2 h[4];
        h[0] = __floats2half2_rn(v0.x, v0.y);
        h[1] = __floats2half2_rn(v0.z, v0.w);
        h[2] = __floats2half2_rn(v1.x, v1.y);
        h[3] = __floats2half2_rn(v1.z, v1.w);
        *reinterpret_cast<uint4*>(g_W + ((gate << 21) | (k << 10)) + 8 * t7) =
            *reinterpret_cast<uint4*>(h);
    }
}

// ---------------- fused GEMM + LSTM cell (R14 shape + chunk-level b hoist) ----------------
__global__ void __launch_bounds__(THREADS, 2)
lstm_fused(const int* __restrict__ caro,
           const float* __restrict__ bf, const float* __restrict__ bi,
           const float* __restrict__ bo, const float* __restrict__ bc,
           float* __restrict__ out)
{
    extern __shared__ __align__(1024) char smem[];
    const uint32_t sbase = smem_u32(smem);
    const int tid = threadIdx.x, wid = tid >> 5, lane = tid & 31;

    const uint32_t n0 = (blockIdx.x & 31) * BN;
    const uint32_t m0 = (blockIdx.x >> 5) * BM;

    const uint32_t gate = wid >> 1;               // warp -> gate
    const int warp_m = (wid & 1) * 64;            // warp -> m half

    float acc[4][4][4];
    #pragma unroll
    for (int mi = 0; mi < 4; ++mi)
        #pragma unroll
        for (int j = 0; j < 4; ++j)
            #pragma unroll
            for (int e = 0; e < 4; ++e) acc[mi][j][e] = 0.f;

    auto stageA = [&](int cs, uint32_t sb, int half) {
        const uint32_t k0 = (uint32_t)cs * BK;
        #pragma unroll
        for (int i = half * 2; i < half * 2 + 2; ++i) {
            const uint32_t idx = (uint32_t)(i * THREADS + tid);
            const uint32_t r = idx >> 3, c = idx & 7;
            cpasync16(sb + sw128((r << 7) + (c << 4)),
                      g_XH + (((m0 + r) << 11) + k0 + (c << 3)));
        }
    };
    auto stageB = [&](int cs, uint32_t sb, int half) {
        const uint32_t k0 = (uint32_t)cs * BK;
        #pragma unroll
        for (int i = half * 2; i < half * 2 + 2; ++i) {
            const uint32_t idx = (uint32_t)(i * THREADS + tid);
            const uint32_t g = idx >> 8, u = idx & 255;
            const uint32_t r = u >> 2, c = u & 3;
            cpasync16(sb + A_BYTES + g * BG_BYTES + r * BG_STRIDE + (c << 4),
                      g_W + ((g << 21) + ((k0 + r) << 10) + n0 + (c << 3)));
        }
    };
    auto stageAll = [&](int cs, uint32_t sb) {
        stageA(cs, sb, 0); stageA(cs, sb, 1);
        stageB(cs, sb, 0); stageB(cs, sb, 1);
    };

    // prologue: stage chunks 0 and 1; wait for 0
    stageAll(0, sbase);        cpcommit();
    stageAll(1, sbase + STG);  cpcommit();
    cpwait<1>();
    __syncthreads();

    #pragma unroll 1
    for (int cc = 0; cc < CHUNKS; ++cc) {
        const uint32_t Ab = sbase + (uint32_t)((cc % 3) * STG);
        const uint32_t Bb = Ab + A_BYTES + gate * BG_BYTES;
        const bool pf = (cc + 2 < CHUNKS);
        const uint32_t sbN = sbase + (uint32_t)(((cc + 2) % 3) * STG);

        // chunk-level b hoist: all 8 ldsm4t up front (32 regs), removing the
        // per-ks b short-scoreboard stall before each mma block
        uint32_t ball[4][2][4];
        #pragma unroll
        for (int ks = 0; ks < 4; ++ks)
            #pragma unroll
            for (int nb = 0; nb < 2; ++nb)
                ldsm4t(ball[ks][nb], Bb + (uint32_t)((ks * 16 + (lane & 15)) * BG_STRIDE
                                                     + (nb * 16 + ((lane >> 4) << 3)) * 2));

        #pragma unroll
        for (int ks = 0; ks < 4; ++ks) {
            uint32_t a[4][4];
            #pragma unroll
            for (int mi = 0; mi < 4; ++mi)
                ldsm4(a[mi], Ab + sw128((uint32_t)((warp_m + 16 * mi + (lane & 15)) * 128
                                                    + ks * 32 + ((lane >> 4) << 4))));

            // interleaved staging of chunk cc+2 (smooth LTS demand)
            if (pf) {
                if (ks == 0)      stageA(cc + 2, sbN, 0);
                else if (ks == 1) stageA(cc + 2, sbN, 1);
                else if (ks == 2) stageB(cc + 2, sbN, 0);
                else              stageB(cc + 2, sbN, 1);
            }

            // hoisted chunk boundary before last mma block (proven safe/neutral)
            if (ks == 3) {
                cpcommit();
                cpwait<1>();
                __syncthreads();
            }

            #pragma unroll
            for (int mi = 0; mi < 4; ++mi)
                #pragma unroll
                for (int j = 0; j < 4; ++j)
                    mma16(acc[mi][j], a[mi],
                          ball[ks][j >> 1][(j & 1) * 2], ball[ks][j >> 1][(j & 1) * 2 + 1]);
        }
    }

    // -------- exchange z through smem (staging buffers dead) --------
    __syncthreads();
    float* zs = reinterpret_cast<float*>(smem);   // [4][128][36]
    #pragma unroll
    for (int mi = 0; mi < 4; ++mi) {
        #pragma unroll
        for (int j = 0; j < 4; ++j) {
            const int r = warp_m + 16 * mi + (lane >> 2);
            const int c = 8 * j + (lane & 3) * 2;
            float* p0 = zs + gate * ZS_G + (uint32_t)r * 36 + c;
            p0[0] = acc[mi][j][0];
            p0[1] = acc[mi][j][1];
            float* p1 = p0 + 8 * 36;
            p1[0] = acc[mi][j][2];
            p1[1] = acc[mi][j][3];
        }
    }
    __syncthreads();

    // -------- combine: activations + h,c stores --------
    const float cf = (float)__ldg(caro);
    const int nloc = (tid & 7) * 4;
    const float4 b_f = *reinterpret_cast<const float4*>(bf + n0 + nloc);
    const float4 b_i = *reinterpret_cast<const float4*>(bi + n0 + nloc);
    const float4 b_o = *reinterpret_cast<const float4*>(bo + n0 + nloc);
    const float4 b_c = *reinterpret_cast<const float4*>(bc + n0 + nloc);

    #pragma unroll
    for (int p = 0; p < 4; ++p) {
        const int m = p * 32 + (tid >> 3);
        const uint32_t zoff = (uint32_t)m * 36 + nloc;
        const float4 zf = *reinterpret_cast<const float4*>(zs + 0 * ZS_G + zoff);
        const float4 zi = *reinterpret_cast<const float4*>(zs + 1 * ZS_G + zoff);
        const float4 zo = *reinterpret_cast<const float4*>(zs + 2 * ZS_G + zoff);
        const float4 zc = *reinterpret_cast<const float4*>(zs + 3 * ZS_G + zoff);

        float4 h4, c4;
        const float* pzf = &zf.x; const float* pzi = &zi.x;
        const float* pzo = &zo.x; const float* pzc = &zc.x;
        const float* pbf = &b_f.x; const float* pbi = &b_i.x;
        const float* pbo = &b_o.x; const float* pbc = &b_c.x;
        float* ph = &h4.x; float* pc = &c4.x;
        #pragma unroll
        for (int e = 0; e < 4; ++e) {
            const float f  = 1.f / (1.f + expf(-(pzf[e] + pbf[e])));
            const float ii = 1.f / (1.f + expf(-(pzi[e] + pbi[e])));
            const float oo = 1.f / (1.f + expf(-(pzo[e] + pbo[e])));
            const float gg = tanhf(pzc[e] + pbc[e]);
            const float cv = f * cf + ii * gg;
            pc[e] = cv;
            ph[e] = oo * cv;
        }
        const size_t o = (size_t)(m0 + m) * DIMK + n0 + nloc;
        *reinterpret_cast<float4*>(out + o) = h4;
        *reinterpret_cast<float4*>(out + PLANE + o) = c4;
    }
}

// ---------------- launch ----------------
extern "C" void kernel_launch(void* const* d_in, const int* in_sizes, int n_in,
                              void* d_out, int out_size) {
    (void)in_sizes; (void)n_in; (void)out_size;
    const float* X    = (const float*)d_in[0];
    const float* H    = (const float*)d_in[1];
    const int*   caro = (const int*)d_in[2];
    const float* Wfx = (const float*)d_in[3];
    const float* Wfh = (const float*)d_in[4];
    const float* bf  = (const float*)d_in[5];
    const float* Wix = (const float*)d_in[6];
    const float* Wih = (const float*)d_in[7];
    const float* bi  = (const float*)d_in[8];
    const float* Wox = (const float*)d_in[9];
    const float* Woh = (const float*)d_in[10];
    const float* bo  = (const float*)d_in[11];
    const float* Wcx = (const float*)d_in[12];
    const float* Wch = (const float*)d_in[13];
    const float* bc  = (const float*)d_in[14];
    float* out = (float*)d_out;

    cudaFuncSetAttribute(lstm_fused, cudaFuncAttributeMaxDynamicSharedMemorySize, SMEM_TOTAL);

    convAll<<<BATCH + 4096, 256>>>(X, H, Wfx, Wfh, Wix, Wih, Wox, Woh, Wcx, Wch);
    lstm_fused<<<(BATCH / BM) * 32, THREADS, SMEM_TOTAL>>>(caro, bf, bi, bo, bc, out);
}

// round 16
// speedup vs baseline: 1.2070x; 1.2070x over previous
#include <cuda_runtime.h>
#include <cuda_fp16.h>
#include <cstdint>
#include <cstddef>

#define DI __device__ __forceinline__

// ---------------- constants ----------------
constexpr int BM = 128, BN = 32, BK = 64, THREADS = 256;
constexpr int DIMK = 1024;
constexpr int BATCH = 16384;
constexpr int KTOT = 2048;
constexpr int CHUNKS = 32;                        // 2048 / 64
constexpr size_t PLANE = (size_t)BATCH * DIMK;

// A: sw128-swizzled rows of 128B (64 halves). B: 4 gate tiles, 64k x 32n, stride 80.
constexpr uint32_t A_BYTES  = 128 * 128;          // 16384
constexpr uint32_t BG_STRIDE = 80;                // 64B data + 16B pad
constexpr uint32_t BG_BYTES  = 64 * BG_STRIDE;    // 5120 per gate
constexpr uint32_t B_BYTES   = 4 * BG_BYTES;      // 20480
constexpr uint32_t STG = A_BYTES + B_BYTES;       // 36864
constexpr uint32_t SMEM_TOTAL = 3 * STG;          // 110592 -> 2 CTAs/SM (216KB)

// z-exchange layout in reused smem: [gate][128][36] floats
constexpr uint32_t ZS_G = 128 * 36;

// ---------------- device scratch ----------------
__device__ __half g_XH[(size_t)BATCH * KTOT];     // [m][k]: X | H   (uint32-addressable)
__device__ __half g_W[(size_t)4 * KTOT * DIMK];   // [gate][k][n]    (uint32-addressable)

// ---------------- PTX helpers ----------------
DI uint32_t smem_u32(const void* p) {
    uint32_t a;
    asm("{ .reg .u64 t; cvta.to.shared.u64 t, %1; cvt.u32.u64 %0, t; }" : "=r"(a) : "l"(p));
    return a;
}
DI uint32_t sw128(uint32_t o) { return o ^ ((o >> 3) & 0x70); }
DI void cpasync16(uint32_t dst, const void* src) {
    asm volatile("cp.async.cg.shared.global [%0], [%1], 16;" :: "r"(dst), "l"(src) : "memory");
}
DI void cpcommit() { asm volatile("cp.async.commit_group;" ::: "memory"); }
template<int N> DI void cpwait() { asm volatile("cp.async.wait_group %0;" :: "n"(N) : "memory"); }
DI void ldsm4(uint32_t* r, uint32_t a) {
    asm volatile("ldmatrix.sync.aligned.m8n8.x4.shared.b16 {%0,%1,%2,%3}, [%4];"
                 : "=r"(r[0]), "=r"(r[1]), "=r"(r[2]), "=r"(r[3]) : "r"(a));
}
DI void ldsm4t(uint32_t* r, uint32_t a) {
    asm volatile("ldmatrix.sync.aligned.m8n8.x4.trans.shared.b16 {%0,%1,%2,%3}, [%4];"
                 : "=r"(r[0]), "=r"(r[1]), "=r"(r[2]), "=r"(r[3]) : "r"(a));
}
DI void mma16(float* d, const uint32_t* a, uint32_t b0, uint32_t b1) {
    asm volatile(
        "mma.sync.aligned.m16n8k16.row.col.f32.f16.f16.f32 "
        "{%0,%1,%2,%3},{%4,%5,%6,%7},{%8,%9},{%0,%1,%2,%3};"
        : "+f"(d[0]), "+f"(d[1]), "+f"(d[2]), "+f"(d[3])
        : "r"(a[0]), "r"(a[1]), "r"(a[2]), "r"(a[3]), "r"(b0), "r"(b1));
}

// ---------------- merged prep: fp16 conversion of X|H and W ----------------
__global__ void __launch_bounds__(256)
convAll(const float* __restrict__ X, const float* __restrict__ H,
        const float* __restrict__ Wfx, const float* __restrict__ Wfh,
        const float* __restrict__ Wix, const float* __restrict__ Wih,
        const float* __restrict__ Wox, const float* __restrict__ Woh,
        const float* __restrict__ Wcx, const float* __restrict__ Wch)
{
    const int t = threadIdx.x;
    if (blockIdx.x < BATCH) {
        const uint32_t m = blockIdx.x;
        const float* src = (t < 128) ? X + ((size_t)m << 10) + 8 * t
                                     : H + ((size_t)m << 10) + 8 * (t - 128);
        const float4 v0 = reinterpret_cast<const float4*>(src)[0];
        const float4 v1 = reinterpret_cast<const float4*>(src)[1];
        __half2 h[4];
        h[0] = __floats2half2_rn(v0.x, v0.y);
        h[1] = __floats2half2_rn(v0.z, v0.w);
        h[2] = __floats2half2_rn(v1.x, v1.y);
        h[3] = __floats2half2_rn(v1.z, v1.w);
        *reinterpret_cast<uint4*>(g_XH + ((uint32_t)m << 11) + 8 * t) = *reinterpret_cast<uint4*>(h);
    } else {
        const uint32_t row = (blockIdx.x - BATCH) * 2 + (t >> 7);   // 2 W-rows per block
        const uint32_t gate = row >> 11;
        const uint32_t k = row & 2047;
        const uint32_t t7 = t & 127;
        const float* Wx = (gate == 0) ? Wfx : (gate == 1) ? Wix : (gate == 2) ? Wox : Wcx;
        const float* Wh = (gate == 0) ? Wfh : (gate == 1) ? Wih : (gate == 2) ? Woh : Wch;
        const float* src = ((k < 1024) ? Wx + ((size_t)k << 10)
                                       : Wh + ((size_t)(k - 1024) << 10)) + 8 * t7;
        const float4 v0 = reinterpret_cast<const float4*>(src)[0];
        const float4 v1 = reinterpret_cast<const float4*>(src)[1];
        __half2 h[4];
        h[0] = __floats2half2_rn(v0.x, v0.y);
        h[1] = __floats2half2_rn(v0.z, v0.w);
        h[2] = __floats2half2_rn(v1.x, v1.y);
        h[3] = __floats2half2_rn(v1.z, v1.w);
        *reinterpret_cast<uint4*>(g_W + ((gate << 21) | (k << 10)) + 8 * t7) =
            *reinterpret_cast<uint4*>(h);
    }
}

// ---------------- fused GEMM + LSTM cell (R14: the established optimum) ----------------
__global__ void __launch_bounds__(THREADS, 2)
lstm_fused(const int* __restrict__ caro,
           const float* __restrict__ bf, const float* __restrict__ bi,
           const float* __restrict__ bo, const float* __restrict__ bc,
           float* __restrict__ out)
{
    extern __shared__ __align__(1024) char smem[];
    const uint32_t sbase = smem_u32(smem);
    const int tid = threadIdx.x, wid = tid >> 5, lane = tid & 31;

    const uint32_t n0 = (blockIdx.x & 31) * BN;
    const uint32_t m0 = (blockIdx.x >> 5) * BM;

    const uint32_t gate = wid >> 1;               // warp -> gate
    const int warp_m = (wid & 1) * 64;            // warp -> m half

    float acc[4][4][4];
    #pragma unroll
    for (int mi = 0; mi < 4; ++mi)
        #pragma unroll
        for (int j = 0; j < 4; ++j)
            #pragma unroll
            for (int e = 0; e < 4; ++e) acc[mi][j][e] = 0.f;

    auto stageA = [&](int cs, uint32_t sb, int half) {
        const uint32_t k0 = (uint32_t)cs * BK;
        #pragma unroll
        for (int i = half * 2; i < half * 2 + 2; ++i) {
            const uint32_t idx = (uint32_t)(i * THREADS + tid);
            const uint32_t r = idx >> 3, c = idx & 7;
            cpasync16(sb + sw128((r << 7) + (c << 4)),
                      g_XH + (((m0 + r) << 11) + k0 + (c << 3)));
        }
    };
    auto stageB = [&](int cs, uint32_t sb, int half) {
        const uint32_t k0 = (uint32_t)cs * BK;
        #pragma unroll
        for (int i = half * 2; i < half * 2 + 2; ++i) {
            const uint32_t idx = (uint32_t)(i * THREADS + tid);
            const uint32_t g = idx >> 8, u = idx & 255;
            const uint32_t r = u >> 2, c = u & 3;
            cpasync16(sb + A_BYTES + g * BG_BYTES + r * BG_STRIDE + (c << 4),
                      g_W + ((g << 21) + ((k0 + r) << 10) + n0 + (c << 3)));
        }
    };
    auto stageAll = [&](int cs, uint32_t sb) {
        stageA(cs, sb, 0); stageA(cs, sb, 1);
        stageB(cs, sb, 0); stageB(cs, sb, 1);
    };

    // prologue: stage chunks 0 and 1; wait for 0
    stageAll(0, sbase);        cpcommit();
    stageAll(1, sbase + STG);  cpcommit();
    cpwait<1>();
    __syncthreads();

    #pragma unroll 1
    for (int cc = 0; cc < CHUNKS; ++cc) {
        const uint32_t Ab = sbase + (uint32_t)((cc % 3) * STG);
        const uint32_t Bb = Ab + A_BYTES + gate * BG_BYTES;
        const bool pf = (cc + 2 < CHUNKS);
        const uint32_t sbN = sbase + (uint32_t)(((cc + 2) % 3) * STG);

        #pragma unroll
        for (int ks = 0; ks < 4; ++ks) {
            uint32_t a[4][4];
            #pragma unroll
            for (int mi = 0; mi < 4; ++mi)
                ldsm4(a[mi], Ab + sw128((uint32_t)((warp_m + 16 * mi + (lane & 15)) * 128
                                                    + ks * 32 + ((lane >> 4) << 4))));
            uint32_t b[2][4];
            #pragma unroll
            for (int nb = 0; nb < 2; ++nb)
                ldsm4t(b[nb], Bb + (uint32_t)((ks * 16 + (lane & 15)) * BG_STRIDE
                                               + (nb * 16 + ((lane >> 4) << 3)) * 2));

            // interleaved staging of chunk cc+2 (smooth LTS demand)
            if (pf) {
                if (ks == 0)      stageA(cc + 2, sbN, 0);
                else if (ks == 1) stageA(cc + 2, sbN, 1);
                else if (ks == 2) stageB(cc + 2, sbN, 0);
                else              stageB(cc + 2, sbN, 1);
            }

            // chunk-boundary hoisted before the last mma block (proven safe)
            if (ks == 3) {
                cpcommit();
                cpwait<1>();
                __syncthreads();
            }

            #pragma unroll
            for (int mi = 0; mi < 4; ++mi)
                #pragma unroll
                for (int j = 0; j < 4; ++j)
                    mma16(acc[mi][j], a[mi], b[j >> 1][(j & 1) * 2], b[j >> 1][(j & 1) * 2 + 1]);
        }
    }

    // -------- exchange z through smem (staging buffers dead) --------
    __syncthreads();
    float* zs = reinterpret_cast<float*>(smem);   // [4][128][36]
    #pragma unroll
    for (int mi = 0; mi < 4; ++mi) {
        #pragma unroll
        for (int j = 0; j < 4; ++j) {
            const int r = warp_m + 16 * mi + (lane >> 2);
            const int c = 8 * j + (lane & 3) * 2;
            float* p0 = zs + gate * ZS_G + (uint32_t)r * 36 + c;
            p0[0] = acc[mi][j][0];
            p0[1] = acc[mi][j][1];
            float* p1 = p0 + 8 * 36;
            p1[0] = acc[mi][j][2];
            p1[1] = acc[mi][j][3];
        }
    }
    __syncthreads();

    // -------- combine: activations + h,c stores --------
    const float cf = (float)__ldg(caro);
    const int nloc = (tid & 7) * 4;
    const float4 b_f = *reinterpret_cast<const float4*>(bf + n0 + nloc);
    const float4 b_i = *reinterpret_cast<const float4*>(bi + n0 + nloc);
    const float4 b_o = *reinterpret_cast<const float4*>(bo + n0 + nloc);
    const float4 b_c = *reinterpret_cast<const float4*>(bc + n0 + nloc);

    #pragma unroll
    for (int p = 0; p < 4; ++p) {
        const int m = p * 32 + (tid >> 3);
        const uint32_t zoff = (uint32_t)m * 36 + nloc;
        const float4 zf = *reinterpret_cast<const float4*>(zs + 0 * ZS_G + zoff);
        const float4 zi = *reinterpret_cast<const float4*>(zs + 1 * ZS_G + zoff);
        const float4 zo = *reinterpret_cast<const float4*>(zs + 2 * ZS_G + zoff);
        const float4 zc = *reinterpret_cast<const float4*>(zs + 3 * ZS_G + zoff);

        float4 h4, c4;
        const float* pzf = &zf.x; const float* pzi = &zi.x;
        const float* pzo = &zo.x; const float* pzc = &zc.x;
        const float* pbf = &b_f.x; const float* pbi = &b_i.x;
        const float* pbo = &b_o.x; const float* pbc = &b_c.x;
        float* ph = &h4.x; float* pc = &c4.x;
        #pragma unroll
        for (int e = 0; e < 4; ++e) {
            const float f  = 1.f / (1.f + expf(-(pzf[e] + pbf[e])));
            const float ii = 1.f / (1.f + expf(-(pzi[e] + pbi[e])));
            const float oo = 1.f / (1.f + expf(-(pzo[e] + pbo[e])));
            const float gg = tanhf(pzc[e] + pbc[e]);
            const float cv = f * cf + ii * gg;
            pc[e] = cv;
            ph[e] = oo * cv;
        }
        const size_t o = (size_t)(m0 + m) * DIMK + n0 + nloc;
        *reinterpret_cast<float4*>(out + o) = h4;
        *reinterpret_cast<float4*>(out + PLANE + o) = c4;
    }
}

// ---------------- launch ----------------
extern "C" void kernel_launch(void* const* d_in, const int* in_sizes, int n_in,
                              void* d_out, int out_size) {
    (void)in_sizes; (void)n_in; (void)out_size;
    const float* X    = (const float*)d_in[0];
    const float* H    = (const float*)d_in[1];
    const int*   caro = (const int*)d_in[2];
    const float* Wfx = (const float*)d_in[3];
    const float* Wfh = (const float*)d_in[4];
    const float* bf  = (const float*)d_in[5];
    const float* Wix = (const float*)d_in[6];
    const float* Wih = (const float*)d_in[7];
    const float* bi  = (const float*)d_in[8];
    const float* Wox = (const float*)d_in[9];
    const float* Woh = (const float*)d_in[10];
    const float* bo  = (const float*)d_in[11];
    const float* Wcx = (const float*)d_in[12];
    const float* Wch = (const float*)d_in[13];
    const float* bc  = (const float*)d_in[14];
    float* out = (float*)d_out;

    cudaFuncSetAttribute(lstm_fused, cudaFuncAttributeMaxDynamicSharedMemorySize, SMEM_TOTAL);

    convAll<<<BATCH + 4096, 256>>>(X, H, Wfx, Wfh, Wix, Wih, Wox, Woh, Wcx, Wch);
    lstm_fused<<<(BATCH / BM) * 32, THREADS, SMEM_TOTAL>>>(caro, bf, bi, bo, bc, out);
}

// round 17
// speedup vs baseline: 1.2624x; 1.0459x over previous
#include <cuda_runtime.h>
#include <cuda_fp16.h>
#include <cstdint>
#include <cstddef>

#define DI __device__ __forceinline__

// ---------------- constants ----------------
constexpr int BM = 128, BN = 32, BK = 64, THREADS = 256;
constexpr int DIMK = 1024;
constexpr int BATCH = 16384;
constexpr int KTOT = 2048;
constexpr int CHUNKS = 32;                        // 2048 / 64
constexpr size_t PLANE = (size_t)BATCH * DIMK;

// A: sw128-swizzled rows of 128B (64 halves). B: 4 gate tiles, 64k x 32n, stride 80.
constexpr uint32_t A_BYTES  = 128 * 128;          // 16384
constexpr uint32_t BG_STRIDE = 80;                // 64B data + 16B pad
constexpr uint32_t BG_BYTES  = 64 * BG_STRIDE;    // 5120 per gate
constexpr uint32_t B_BYTES   = 4 * BG_BYTES;      // 20480
constexpr uint32_t STG = A_BYTES + B_BYTES;       // 36864
constexpr uint32_t SMEM_TOTAL = 3 * STG;          // 110592 -> 2 CTAs/SM (216KB)

// z-exchange layout in reused smem: [gate][128][36] floats
constexpr uint32_t ZS_G = 128 * 36;

// ---------------- device scratch ----------------
__device__ __half g_XH[(size_t)BATCH * KTOT];     // [m][k]: X | H   (uint32-addressable)
__device__ __half g_W[(size_t)4 * KTOT * DIMK];   // [gate][k][n]    (uint32-addressable)

// ---------------- PTX helpers ----------------
DI uint32_t smem_u32(const void* p) {
    uint32_t a;
    asm("{ .reg .u64 t; cvta.to.shared.u64 t, %1; cvt.u32.u64 %0, t; }" : "=r"(a) : "l"(p));
    return a;
}
DI uint32_t sw128(uint32_t o) { return o ^ ((o >> 3) & 0x70); }
DI void cpasync16(uint32_t dst, const void* src) {
    asm volatile("cp.async.cg.shared.global [%0], [%1], 16;" :: "r"(dst), "l"(src) : "memory");
}
DI void cpcommit() { asm volatile("cp.async.commit_group;" ::: "memory"); }
template<int N> DI void cpwait() { asm volatile("cp.async.wait_group %0;" :: "n"(N) : "memory"); }
DI void ldsm4(uint32_t* r, uint32_t a) {
    asm volatile("ldmatrix.sync.aligned.m8n8.x4.shared.b16 {%0,%1,%2,%3}, [%4];"
                 : "=r"(r[0]), "=r"(r[1]), "=r"(r[2]), "=r"(r[3]) : "r"(a));
}
DI void ldsm4t(uint32_t* r, uint32_t a) {
    asm volatile("ldmatrix.sync.aligned.m8n8.x4.trans.shared.b16 {%0,%1,%2,%3}, [%4];"
                 : "=r"(r[0]), "=r"(r[1]), "=r"(r[2]), "=r"(r[3]) : "r"(a));
}
DI void mma16(float* d, const uint32_t* a, uint32_t b0, uint32_t b1) {
    asm volatile(
        "mma.sync.aligned.m16n8k16.row.col.f32.f16.f16.f32 "
        "{%0,%1,%2,%3},{%4,%5,%6,%7},{%8,%9},{%0,%1,%2,%3};"
        : "+f"(d[0]), "+f"(d[1]), "+f"(d[2]), "+f"(d[3])
        : "r"(a[0]), "r"(a[1]), "r"(a[2]), "r"(a[3]), "r"(b0), "r"(b1));
}

// ---------------- merged prep: fp16 conversion of X|H and W ----------------
__global__ void __launch_bounds__(256)
convAll(const float* __restrict__ X, const float* __restrict__ H,
        const float* __restrict__ Wfx, const float* __restrict__ Wfh,
        const float* __restrict__ Wix, const float* __restrict__ Wih,
        const float* __restrict__ Wox, const float* __restrict__ Woh,
        const float* __restrict__ Wcx, const float* __restrict__ Wch)
{
    const int t = threadIdx.x;
    if (blockIdx.x < BATCH) {
        const uint32_t m = blockIdx.x;
        const float* src = (t < 128) ? X + ((size_t)m << 10) + 8 * t
                                     : H + ((size_t)m << 10) + 8 * (t - 128);
        const float4 v0 = reinterpret_cast<const float4*>(src)[0];
        const float4 v1 = reinterpret_cast<const float4*>(src)[1];
        __half2 h[4];
        h[0] = __floats2half2_rn(v0.x, v0.y);
        h[1] = __floats2half2_rn(v0.z, v0.w);
        h[2] = __floats2half2_rn(v1.x, v1.y);
        h[3] = __floats2half2_rn(v1.z, v1.w);
        *reinterpret_cast<uint4*>(g_XH + ((uint32_t)m << 11) + 8 * t) = *reinterpret_cast<uint4*>(h);
    } else {
        const uint32_t row = (blockIdx.x - BATCH) * 2 + (t >> 7);   // 2 W-rows per block
        const uint32_t gate = row >> 11;
        const uint32_t k = row & 2047;
        const uint32_t t7 = t & 127;
        const float* Wx = (gate == 0) ? Wfx : (gate == 1) ? Wix : (gate == 2) ? Wox : Wcx;
        const float* Wh = (gate == 0) ? Wfh : (gate == 1) ? Wih : (gate == 2) ? Woh : Wch;
        const float* src = ((k < 1024) ? Wx + ((size_t)k << 10)
                                       : Wh + ((size_t)(k - 1024) << 10)) + 8 * t7;
        const float4 v0 = reinterpret_cast<const float4*>(src)[0];
        const float4 v1 = reinterpret_cast<const float4*>(src)[1];
        __half2 h[4];
        h[0] = __floats2half2_rn(v0.x, v0.y);
        h[1] = __floats2half2_rn(v0.z, v0.w);
        h[2] = __floats2half2_rn(v1.x, v1.y);
        h[3] = __floats2half2_rn(v1.z, v1.w);
        *reinterpret_cast<uint4*>(g_W + ((gate << 21) | (k << 10)) + 8 * t7) =
            *reinterpret_cast<uint4*>(h);
    }
}

// ---------------- fused GEMM + LSTM cell (R14 + unroll-2 mainloop) ----------------
__global__ void __launch_bounds__(THREADS, 2)
lstm_fused(const int* __restrict__ caro,
           const float* __restrict__ bf, const float* __restrict__ bi,
           const float* __restrict__ bo, const float* __restrict__ bc,
           float* __restrict__ out)
{
    extern __shared__ __align__(1024) char smem[];
    const uint32_t sbase = smem_u32(smem);
    const int tid = threadIdx.x, wid = tid >> 5, lane = tid & 31;

    const uint32_t n0 = (blockIdx.x & 31) * BN;
    const uint32_t m0 = (blockIdx.x >> 5) * BM;

    const uint32_t gate = wid >> 1;               // warp -> gate
    const int warp_m = (wid & 1) * 64;            // warp -> m half

    float acc[4][4][4];
    #pragma unroll
    for (int mi = 0; mi < 4; ++mi)
        #pragma unroll
        for (int j = 0; j < 4; ++j)
            #pragma unroll
            for (int e = 0; e < 4; ++e) acc[mi][j][e] = 0.f;

    auto stageA = [&](int cs, uint32_t sb, int half) {
        const uint32_t k0 = (uint32_t)cs * BK;
        #pragma unroll
        for (int i = half * 2; i < half * 2 + 2; ++i) {
            const uint32_t idx = (uint32_t)(i * THREADS + tid);
            const uint32_t r = idx >> 3, c = idx & 7;
            cpasync16(sb + sw128((r << 7) + (c << 4)),
                      g_XH + (((m0 + r) << 11) + k0 + (c << 3)));
        }
    };
    auto stageB = [&](int cs, uint32_t sb, int half) {
        const uint32_t k0 = (uint32_t)cs * BK;
        #pragma unroll
        for (int i = half * 2; i < half * 2 + 2; ++i) {
            const uint32_t idx = (uint32_t)(i * THREADS + tid);
            const uint32_t g = idx >> 8, u = idx & 255;
            const uint32_t r = u >> 2, c = u & 3;
            cpasync16(sb + A_BYTES + g * BG_BYTES + r * BG_STRIDE + (c << 4),
                      g_W + ((g << 21) + ((k0 + r) << 10) + n0 + (c << 3)));
        }
    };
    auto stageAll = [&](int cs, uint32_t sb) {
        stageA(cs, sb, 0); stageA(cs, sb, 1);
        stageB(cs, sb, 0); stageB(cs, sb, 1);
    };

    // prologue: stage chunks 0 and 1; wait for 0
    stageAll(0, sbase);        cpcommit();
    stageAll(1, sbase + STG);  cpcommit();
    cpwait<1>();
    __syncthreads();

    // unroll 2: expose adjacent chunk bodies to ptxas so the next chunk's frag
    // loads can issue in the tensor-drain shadow after the hoisted barrier
    #pragma unroll 2
    for (int cc = 0; cc < CHUNKS; ++cc) {
        const uint32_t Ab = sbase + (uint32_t)((cc % 3) * STG);
        const uint32_t Bb = Ab + A_BYTES + gate * BG_BYTES;
        const bool pf = (cc + 2 < CHUNKS);
        const uint32_t sbN = sbase + (uint32_t)(((cc + 2) % 3) * STG);

        #pragma unroll
        for (int ks = 0; ks < 4; ++ks) {
            uint32_t a[4][4];
            #pragma unroll
            for (int mi = 0; mi < 4; ++mi)
                ldsm4(a[mi], Ab + sw128((uint32_t)((warp_m + 16 * mi + (lane & 15)) * 128
                                                    + ks * 32 + ((lane >> 4) << 4))));
            uint32_t b[2][4];
            #pragma unroll
            for (int nb = 0; nb < 2; ++nb)
                ldsm4t(b[nb], Bb + (uint32_t)((ks * 16 + (lane & 15)) * BG_STRIDE
                                               + (nb * 16 + ((lane >> 4) << 3)) * 2));

            // interleaved staging of chunk cc+2 (smooth LTS demand)
            if (pf) {
                if (ks == 0)      stageA(cc + 2, sbN, 0);
                else if (ks == 1) stageA(cc + 2, sbN, 1);
                else if (ks == 2) stageB(cc + 2, sbN, 0);
                else              stageB(cc + 2, sbN, 1);
            }

            // chunk-boundary hoisted before the last mma block (proven safe)
            if (ks == 3) {
                cpcommit();
                cpwait<1>();
                __syncthreads();
            }

            #pragma unroll
            for (int mi = 0; mi < 4; ++mi)
                #pragma unroll
                for (int j = 0; j < 4; ++j)
                    mma16(acc[mi][j], a[mi], b[j >> 1][(j & 1) * 2], b[j >> 1][(j & 1) * 2 + 1]);
        }
    }

    // -------- exchange z through smem (staging buffers dead) --------
    __syncthreads();
    float* zs = reinterpret_cast<float*>(smem);   // [4][128][36]
    #pragma unroll
    for (int mi = 0; mi < 4; ++mi) {
        #pragma unroll
        for (int j = 0; j < 4; ++j) {
            const int r = warp_m + 16 * mi + (lane >> 2);
            const int c = 8 * j + (lane & 3) * 2;
            float* p0 = zs + gate * ZS_G + (uint32_t)r * 36 + c;
            p0[0] = acc[mi][j][0];
            p0[1] = acc[mi][j][1];
            float* p1 = p0 + 8 * 36;
            p1[0] = acc[mi][j][2];
            p1[1] = acc[mi][j][3];
        }
    }
    __syncthreads();

    // -------- combine: activations + h,c stores --------
    const float cf = (float)__ldg(caro);
    const int nloc = (tid & 7) * 4;
    const float4 b_f = *reinterpret_cast<const float4*>(bf + n0 + nloc);
    const float4 b_i = *reinterpret_cast<const float4*>(bi + n0 + nloc);
    const float4 b_o = *reinterpret_cast<const float4*>(bo + n0 + nloc);
    const float4 b_c = *reinterpret_cast<const float4*>(bc + n0 + nloc);

    #pragma unroll
    for (int p = 0; p < 4; ++p) {
        const int m = p * 32 + (tid >> 3);
        const uint32_t zoff = (uint32_t)m * 36 + nloc;
        const float4 zf = *reinterpret_cast<const float4*>(zs + 0 * ZS_G + zoff);
        const float4 zi = *reinterpret_cast<const float4*>(zs + 1 * ZS_G + zoff);
        const float4 zo = *reinterpret_cast<const float4*>(zs + 2 * ZS_G + zoff);
        const float4 zc = *reinterpret_cast<const float4*>(zs + 3 * ZS_G + zoff);

        float4 h4, c4;
        const float* pzf = &zf.x; const float* pzi = &zi.x;
        const float* pzo = &zo.x; const float* pzc = &zc.x;
        const float* pbf = &b_f.x; const float* pbi = &b_i.x;
        const float* pbo = &b_o.x; const float* pbc = &b_c.x;
        float* ph = &h4.x; float* pc = &c4.x;
        #pragma unroll
        for (int e = 0; e < 4; ++e) {
            const float f  = 1.f / (1.f + expf(-(pzf[e] + pbf[e])));
            const float ii = 1.f / (1.f + expf(-(pzi[e] + pbi[e])));
            const float oo = 1.f / (1.f + expf(-(pzo[e] + pbo[e])));
            const float gg = tanhf(pzc[e] + pbc[e]);
            const float cv = f * cf + ii * gg;
            pc[e] = cv;
            ph[e] = oo * cv;
        }
        const size_t o = (size_t)(m0 + m) * DIMK + n0 + nloc;
        *reinterpret_cast<float4*>(out + o) = h4;
        *reinterpret_cast<float4*>(out + PLANE + o) = c4;
    }
}

// ---------------- launch ----------------
extern "C" void kernel_launch(void* const* d_in, const int* in_sizes, int n_in,
                              void* d_out, int out_size) {
    (void)in_sizes; (void)n_in; (void)out_size;
    const float* X    = (const float*)d_in[0];
    const float* H    = (const float*)d_in[1];
    const int*   caro = (const int*)d_in[2];
    const float* Wfx = (const float*)d_in[3];
    const float* Wfh = (const float*)d_in[4];
    const float* bf  = (const float*)d_in[5];
    const float* Wix = (const float*)d_in[6];
    const float* Wih = (const float*)d_in[7];
    const float* bi  = (const float*)d_in[8];
    const float* Wox = (const float*)d_in[9];
    const float* Woh = (const float*)d_in[10];
    const float* bo  = (const float*)d_in[11];
    const float* Wcx = (const float*)d_in[12];
    const float* Wch = (const float*)d_in[13];
    const float* bc  = (const float*)d_in[14];
    float* out = (float*)d_out;

    cudaFuncSetAttribute(lstm_fused, cudaFuncAttributeMaxDynamicSharedMemorySize, SMEM_TOTAL);

    convAll<<<BATCH + 4096, 256>>>(X, H, Wfx, Wfh, Wix, Wih, Wox, Woh, Wcx, Wch);
    lstm_fused<<<(BATCH / BM) * 32, THREADS, SMEM_TOTAL>>>(caro, bf, bi, bo, bc, out);
}